// round 3
// baseline (speedup 1.0000x reference)
#include <cuda_runtime.h>
#include <cstdint>

// ---------------------------------------------------------------------------
// Scratch (static __device__ — no allocation in kernel_launch)
// ---------------------------------------------------------------------------
static __device__ float g_Y[8 * 1152 * 1024];  // fused QKV output [b][1152][1024]
static __device__ float g_O[8 * 384 * 1024];   // attention output  [b][384][1024]

// ---------------------------------------------------------------------------
// Helpers
// ---------------------------------------------------------------------------
__device__ __forceinline__ unsigned tf32_bits(float x) {
    unsigned u;
    asm("cvt.rna.tf32.f32 %0, %1;" : "=r"(u) : "f"(x));
    return u;
}
__device__ __forceinline__ float tf32f(float x) { return __uint_as_float(tf32_bits(x)); }

__device__ __forceinline__ float fast_ex2(float x) {
    float y;
    asm("ex2.approx.f32 %0, %1;" : "=f"(y) : "f"(x));
    return y;
}

__device__ __forceinline__ void mma_tf32(float* c,
                                         unsigned a0, unsigned a1, unsigned a2, unsigned a3,
                                         unsigned b0, unsigned b1) {
    asm volatile(
        "mma.sync.aligned.m16n8k8.row.col.f32.tf32.tf32.f32 "
        "{%0,%1,%2,%3}, {%4,%5,%6,%7}, {%8,%9}, {%0,%1,%2,%3};\n"
        : "+f"(c[0]), "+f"(c[1]), "+f"(c[2]), "+f"(c[3])
        : "r"(a0), "r"(a1), "r"(a2), "r"(a3), "r"(b0), "r"(b1));
}

// ---------------------------------------------------------------------------
// Generic batched GEMM: C[b][m][n] = sum_k W[m][k] * X[b][k][n] + bias[m]
// K = 384, N = 1024 fixed. Tiles: 128x128, k-chunk 32. 8 warps x (16 rows each).
// ---------------------------------------------------------------------------
__global__ __launch_bounds__(256, 2)
void gemm_tf32_kernel(const float* __restrict__ W, const float* __restrict__ X,
                      const float* __restrict__ bias, float* __restrict__ C,
                      long xStride, long cStride) {
    __shared__ float As[128 * 36];   // [m][k], stride 36 -> conflict-free frags
    __shared__ float Bs[32 * 136];   // [k][n], stride 136 -> conflict-free frags

    const int b  = blockIdx.z;
    const int m0 = blockIdx.y * 128;
    const int n0 = blockIdx.x * 128;
    const float* Xb = X + (long)b * xStride;
    float*       Cb = C + (long)b * cStride;

    const int tid  = threadIdx.x;
    const int warp = tid >> 5, lane = tid & 31;
    const int gr = lane >> 2, tc = lane & 3;

    float acc[16][4];
#pragma unroll
    for (int i = 0; i < 16; i++) { acc[i][0] = 0.f; acc[i][1] = 0.f; acc[i][2] = 0.f; acc[i][3] = 0.f; }

    for (int k0 = 0; k0 < 384; k0 += 32) {
        // A tile 128x32 (row-major global, K=384)
#pragma unroll
        for (int i = 0; i < 4; i++) {
            int idx = tid + i * 256;            // 1024 float4 slots
            int r = idx >> 3, c4 = (idx & 7) << 2;
            const float4 v = *reinterpret_cast<const float4*>(W + (long)(m0 + r) * 384 + k0 + c4);
            float* dst = As + r * 36 + c4;      // stride 36: scalar stores
            dst[0] = tf32f(v.x); dst[1] = tf32f(v.y); dst[2] = tf32f(v.z); dst[3] = tf32f(v.w);
        }
        // B tile 32x128
#pragma unroll
        for (int i = 0; i < 4; i++) {
            int idx = tid + i * 256;
            int r = idx >> 5, c4 = (idx & 31) << 2;
            float4 v = *reinterpret_cast<const float4*>(Xb + (long)(k0 + r) * 1024 + n0 + c4);
            v.x = tf32f(v.x); v.y = tf32f(v.y); v.z = tf32f(v.z); v.w = tf32f(v.w);
            *reinterpret_cast<float4*>(Bs + r * 136 + c4) = v;  // 544B row stride: 16B aligned
        }
        __syncthreads();

#pragma unroll
        for (int ks = 0; ks < 4; ks++) {
            const int kk = ks * 8;
            const int ar = warp * 16 + gr;
            unsigned a0 = __float_as_uint(As[ar * 36 + kk + tc]);
            unsigned a1 = __float_as_uint(As[(ar + 8) * 36 + kk + tc]);
            unsigned a2 = __float_as_uint(As[ar * 36 + kk + tc + 4]);
            unsigned a3 = __float_as_uint(As[(ar + 8) * 36 + kk + tc + 4]);
#pragma unroll
            for (int nt = 0; nt < 16; nt++) {
                unsigned b0 = __float_as_uint(Bs[(kk + tc) * 136 + nt * 8 + gr]);
                unsigned b1 = __float_as_uint(Bs[(kk + tc + 4) * 136 + nt * 8 + gr]);
                mma_tf32(acc[nt], a0, a1, a2, a3, b0, b1);
            }
        }
        __syncthreads();
    }

    const int r0 = m0 + warp * 16 + gr;
    const float bz0 = bias[r0], bz1 = bias[r0 + 8];
#pragma unroll
    for (int nt = 0; nt < 16; nt++) {
        const int cc = n0 + nt * 8 + tc * 2;
        float2 v0 = make_float2(acc[nt][0] + bz0, acc[nt][1] + bz0);
        float2 v1 = make_float2(acc[nt][2] + bz1, acc[nt][3] + bz1);
        *reinterpret_cast<float2*>(Cb + (long)r0 * 1024 + cc)       = v0;
        *reinterpret_cast<float2*>(Cb + (long)(r0 + 8) * 1024 + cc) = v1;
    }
}

// ---------------------------------------------------------------------------
// Flash attention with tf32 mma, analytic relative-position bias.
// Grid: (qblock 0..7, head 0..11, batch 0..7). 256 threads = 8 warps.
// Q,K,V live in g_Y as [d(32)][n(1024)] slices per (b,h).
// Output written transposed to g_O[b][h*32+d][n].
// ---------------------------------------------------------------------------
constexpr int ATTN_SMEM_FLOATS = 32 * 136 + 32 * 136 + 32 * 132 + 128 * 132 + 3969;
constexpr int ATTN_SMEM_BYTES  = ATTN_SMEM_FLOATS * 4;  // 135,172 B

__global__ __launch_bounds__(256, 1)
void attn_kernel(const float* __restrict__ rpb_table, float* __restrict__ Oout) {
    extern __shared__ float sm[];
    float* Qs    = sm;                 // [32][136] tf32, pre-scaled by hd^-0.5
    float* Ks    = Qs + 32 * 136;      // [32][136] tf32
    float* Vs    = Ks + 32 * 136;      // [32][132] tf32
    float* Ps    = Vs + 32 * 132;      // [128][132] tf32 probabilities (reused as O staging)
    float* rpb_s = Ps + 128 * 132;     // [3969] this head's bias table column

    const int qb = blockIdx.x, h = blockIdx.y, b = blockIdx.z;
    const int tid  = threadIdx.x;
    const int warp = tid >> 5, lane = tid & 31;
    const int gr = lane >> 2, tc = lane & 3;

    const float* Qg = g_Y + ((long)b * 1152 + h * 32) * 1024 + qb * 128;
    const float* Kg = g_Y + ((long)b * 1152 + 384 + h * 32) * 1024;
    const float* Vg = g_Y + ((long)b * 1152 + 768 + h * 32) * 1024;

    // Per-head bias table column into shared (stride-12 gather, 15.9 KB)
    for (int i = tid; i < 3969; i += 256) rpb_s[i] = rpb_table[i * 12 + h];

    // Q tile [32 d][128 n], pre-scaled
    const float scale = 0.17677669529663687f;  // 32^-0.5
#pragma unroll
    for (int i = 0; i < 4; i++) {
        int idx = tid + i * 256;
        int d = idx >> 5, c4 = (idx & 31) << 2;
        float4 v = *reinterpret_cast<const float4*>(Qg + (long)d * 1024 + c4);
        v.x = tf32f(v.x * scale); v.y = tf32f(v.y * scale);
        v.z = tf32f(v.z * scale); v.w = tf32f(v.w * scale);
        *reinterpret_cast<float4*>(Qs + d * 136 + c4) = v;
    }

    float oacc[4][4];
#pragma unroll
    for (int i = 0; i < 4; i++) { oacc[i][0] = 0.f; oacc[i][1] = 0.f; oacc[i][2] = 0.f; oacc[i][3] = 0.f; }
    float mrun0 = -1e30f, mrun1 = -1e30f, lrun0 = 0.f, lrun1 = 0.f;

    // Hoisted bias row constants: idx = A_row - (m + (m>>5)*31)
    const int n0g = qb * 128 + warp * 16 + gr;
    const int Abias0 = ((n0g >> 5) + 31) * 63 + (n0g & 31) + 31;
    const int n1g = n0g + 8;
    const int Abias1 = ((n1g >> 5) + 31) * 63 + (n1g & 31) + 31;

    const float L2E = 1.4426950408889634f;

    for (int kb = 0; kb < 8; kb++) {
        // Load K,V blocks [32 d][128 j]
#pragma unroll
        for (int i = 0; i < 4; i++) {
            int idx = tid + i * 256;
            int d = idx >> 5, c4 = (idx & 31) << 2;
            float4 v = *reinterpret_cast<const float4*>(Kg + (long)d * 1024 + kb * 128 + c4);
            v.x = tf32f(v.x); v.y = tf32f(v.y); v.z = tf32f(v.z); v.w = tf32f(v.w);
            *reinterpret_cast<float4*>(Ks + d * 136 + c4) = v;
            float4 w = *reinterpret_cast<const float4*>(Vg + (long)d * 1024 + kb * 128 + c4);
            w.x = tf32f(w.x); w.y = tf32f(w.y); w.z = tf32f(w.z); w.w = tf32f(w.w);
            *reinterpret_cast<float4*>(Vs + d * 132 + c4) = w;
        }
        __syncthreads();

        // S = Q^T K  (warp rows: warp*16..+15, all 128 cols)
        float sacc[16][4];
#pragma unroll
        for (int i = 0; i < 16; i++) { sacc[i][0] = 0.f; sacc[i][1] = 0.f; sacc[i][2] = 0.f; sacc[i][3] = 0.f; }

#pragma unroll
        for (int ks = 0; ks < 4; ks++) {
            const int kk = ks * 8;
            const int nb = warp * 16;
            unsigned a0 = __float_as_uint(Qs[(kk + tc) * 136 + nb + gr]);
            unsigned a1 = __float_as_uint(Qs[(kk + tc) * 136 + nb + gr + 8]);
            unsigned a2 = __float_as_uint(Qs[(kk + tc + 4) * 136 + nb + gr]);
            unsigned a3 = __float_as_uint(Qs[(kk + tc + 4) * 136 + nb + gr + 8]);
#pragma unroll
            for (int nt = 0; nt < 16; nt++) {
                unsigned b0 = __float_as_uint(Ks[(kk + tc) * 136 + nt * 8 + gr]);
                unsigned b1 = __float_as_uint(Ks[(kk + tc + 4) * 136 + nt * 8 + gr]);
                mma_tf32(sacc[nt], a0, a1, a2, a3, b0, b1);
            }
        }

        // Add relative-position bias (analytic index)
#pragma unroll
        for (int nt = 0; nt < 16; nt++) {
            const int m  = kb * 128 + nt * 8 + tc * 2;   // even column
            const int Bm = m + (m >> 5) * 31;
            sacc[nt][0] += rpb_s[Abias0 - Bm];
            sacc[nt][1] += rpb_s[Abias0 - Bm - 1];
            sacc[nt][2] += rpb_s[Abias1 - Bm];
            sacc[nt][3] += rpb_s[Abias1 - Bm - 1];
        }

        // Online softmax: row max (quad-lane reduce), rescale, exp, sum
        float mx0 = -1e30f, mx1 = -1e30f;
#pragma unroll
        for (int nt = 0; nt < 16; nt++) {
            mx0 = fmaxf(mx0, fmaxf(sacc[nt][0], sacc[nt][1]));
            mx1 = fmaxf(mx1, fmaxf(sacc[nt][2], sacc[nt][3]));
        }
        mx0 = fmaxf(mx0, __shfl_xor_sync(0xffffffffu, mx0, 1));
        mx0 = fmaxf(mx0, __shfl_xor_sync(0xffffffffu, mx0, 2));
        mx1 = fmaxf(mx1, __shfl_xor_sync(0xffffffffu, mx1, 1));
        mx1 = fmaxf(mx1, __shfl_xor_sync(0xffffffffu, mx1, 2));
        const float mnew0 = fmaxf(mrun0, mx0);
        const float mnew1 = fmaxf(mrun1, mx1);
        const float alpha0 = fast_ex2((mrun0 - mnew0) * L2E);
        const float alpha1 = fast_ex2((mrun1 - mnew1) * L2E);
        mrun0 = mnew0; mrun1 = mnew1;

        float sum0 = 0.f, sum1 = 0.f;
        const int rl = warp * 16 + gr;
#pragma unroll
        for (int nt = 0; nt < 16; nt++) {
            float p0 = fast_ex2((sacc[nt][0] - mnew0) * L2E);
            float p1 = fast_ex2((sacc[nt][1] - mnew0) * L2E);
            float p2 = fast_ex2((sacc[nt][2] - mnew1) * L2E);
            float p3 = fast_ex2((sacc[nt][3] - mnew1) * L2E);
            sum0 += p0 + p1; sum1 += p2 + p3;
            const int cl = nt * 8 + tc * 2;
            *reinterpret_cast<float2*>(Ps + rl * 132 + cl)       = make_float2(tf32f(p0), tf32f(p1));
            *reinterpret_cast<float2*>(Ps + (rl + 8) * 132 + cl) = make_float2(tf32f(p2), tf32f(p3));
        }
        sum0 += __shfl_xor_sync(0xffffffffu, sum0, 1);
        sum0 += __shfl_xor_sync(0xffffffffu, sum0, 2);
        sum1 += __shfl_xor_sync(0xffffffffu, sum1, 1);
        sum1 += __shfl_xor_sync(0xffffffffu, sum1, 2);
        lrun0 = lrun0 * alpha0 + sum0;
        lrun1 = lrun1 * alpha1 + sum1;
#pragma unroll
        for (int dt = 0; dt < 4; dt++) {
            oacc[dt][0] *= alpha0; oacc[dt][1] *= alpha0;
            oacc[dt][2] *= alpha1; oacc[dt][3] *= alpha1;
        }
        __syncwarp();  // Ps rows of this warp are consumed only by this warp

        // O += P @ V^T  (k = j over 128, cols = d over 32)
#pragma unroll
        for (int ks = 0; ks < 16; ks++) {
            const int kk = ks * 8;
            unsigned a0 = __float_as_uint(Ps[(warp * 16 + gr) * 132 + kk + tc]);
            unsigned a1 = __float_as_uint(Ps[(warp * 16 + gr + 8) * 132 + kk + tc]);
            unsigned a2 = __float_as_uint(Ps[(warp * 16 + gr) * 132 + kk + tc + 4]);
            unsigned a3 = __float_as_uint(Ps[(warp * 16 + gr + 8) * 132 + kk + tc + 4]);
#pragma unroll
            for (int dt = 0; dt < 4; dt++) {
                unsigned b0 = __float_as_uint(Vs[(dt * 8 + gr) * 132 + kk + tc]);
                unsigned b1 = __float_as_uint(Vs[(dt * 8 + gr) * 132 + kk + tc + 4]);
                mma_tf32(oacc[dt], a0, a1, a2, a3, b0, b1);
            }
        }
        __syncthreads();  // protect Ks/Vs (and Ps region) before next iteration
    }

    // Finalize: O /= l, stage transposed, write [d][n] coalesced
    const float inv0 = 1.f / lrun0;
    const float inv1 = 1.f / lrun1;
    float* Os = Ps;  // reuse, stride 33 ([128 n][32 d] + pad)
    {
        const int rl = warp * 16 + gr;
#pragma unroll
        for (int dt = 0; dt < 4; dt++) {
            const int cl = dt * 8 + tc * 2;
            Os[rl * 33 + cl]           = oacc[dt][0] * inv0;
            Os[rl * 33 + cl + 1]       = oacc[dt][1] * inv0;
            Os[(rl + 8) * 33 + cl]     = oacc[dt][2] * inv1;
            Os[(rl + 8) * 33 + cl + 1] = oacc[dt][3] * inv1;
        }
    }
    __syncthreads();
    float* Ob = Oout + ((long)b * 384 + h * 32) * 1024 + qb * 128;
    for (int i = tid; i < 4096; i += 256) {
        int d = i >> 7, n = i & 127;
        Ob[(long)d * 1024 + n] = Os[n * 33 + d];
    }
}

// ---------------------------------------------------------------------------
// Launch
// ---------------------------------------------------------------------------
extern "C" void kernel_launch(void* const* d_in, const int* in_sizes, int n_in,
                              void* d_out, int out_size) {
    (void)in_sizes; (void)n_in; (void)out_size;
    const float* x      = (const float*)d_in[0];
    const float* q_w    = (const float*)d_in[1];
    const float* q_b    = (const float*)d_in[2];
    const float* kv_w   = (const float*)d_in[3];
    const float* kv_b   = (const float*)d_in[4];
    const float* proj_w = (const float*)d_in[5];
    const float* proj_b = (const float*)d_in[6];
    const float* rpb    = (const float*)d_in[7];
    // d_in[8] = rel_index: recomputed analytically on device, unused.
    float* out = (float*)d_out;

    float* Y = nullptr; cudaGetSymbolAddress((void**)&Y, g_Y);
    float* O = nullptr; cudaGetSymbolAddress((void**)&O, g_O);

    cudaFuncSetAttribute(attn_kernel, cudaFuncAttributeMaxDynamicSharedMemorySize,
                         ATTN_SMEM_BYTES);

    dim3 blk(256);
    // QKV projections -> g_Y rows [0:384)=Q, [384:768)=K, [768:1152)=V per batch
    gemm_tf32_kernel<<<dim3(8, 3, 8), blk>>>(q_w,  x, q_b,  Y,               384L * 1024, 1152L * 1024);
    gemm_tf32_kernel<<<dim3(8, 6, 8), blk>>>(kv_w, x, kv_b, Y + 384 * 1024, 384L * 1024, 1152L * 1024);
    // Flash attention -> g_O[b][c][n]
    attn_kernel<<<dim3(8, 12, 8), blk, ATTN_SMEM_BYTES>>>(rpb, O);
    // Output projection -> d_out
    gemm_tf32_kernel<<<dim3(8, 3, 8), blk>>>(proj_w, O, proj_b, out, 384L * 1024, 384L * 1024);
}

// round 9
// speedup vs baseline: 1.2774x; 1.2774x over previous
#include <cuda_runtime.h>
#include <cstdint>

// ---------------------------------------------------------------------------
// Scratch (static __device__ — no allocation in kernel_launch)
// ---------------------------------------------------------------------------
static __device__ float g_X[8 * 384 * 1024];   // tf32-rounded input activations
static __device__ float g_Y[8 * 1152 * 1024];  // fused QKV output [b][1152][1024] (tf32-rounded)
static __device__ float g_O[8 * 384 * 1024];   // attention output  [b][384][1024] (tf32-rounded)
static __device__ float g_Wqkv[1152 * 384];    // [q_w*scale ; kv_w] tf32-rounded
static __device__ float g_Wp[384 * 384];       // proj_w tf32-rounded
static __device__ float g_Bqkv[1152];          // [q_b*scale ; kv_b]

// ---------------------------------------------------------------------------
// Helpers
// ---------------------------------------------------------------------------
__device__ __forceinline__ unsigned tf32_bits(float x) {
    unsigned u;
    asm("cvt.rna.tf32.f32 %0, %1;" : "=r"(u) : "f"(x));
    return u;
}
__device__ __forceinline__ float tf32f(float x) { return __uint_as_float(tf32_bits(x)); }

__device__ __forceinline__ float fast_ex2(float x) {
    float y;
    asm("ex2.approx.f32 %0, %1;" : "=f"(y) : "f"(x));
    return y;
}

__device__ __forceinline__ void mma_tf32(float* c,
                                         unsigned a0, unsigned a1, unsigned a2, unsigned a3,
                                         unsigned b0, unsigned b1) {
    asm volatile(
        "mma.sync.aligned.m16n8k8.row.col.f32.tf32.tf32.f32 "
        "{%0,%1,%2,%3}, {%4,%5,%6,%7}, {%8,%9}, {%0,%1,%2,%3};\n"
        : "+f"(c[0]), "+f"(c[1]), "+f"(c[2]), "+f"(c[3])
        : "r"(a0), "r"(a1), "r"(a2), "r"(a3), "r"(b0), "r"(b1));
}

__device__ __forceinline__ void cp_async16(float* smem_dst, const float* gmem_src) {
    unsigned s = (unsigned)__cvta_generic_to_shared(smem_dst);
    asm volatile("cp.async.cg.shared.global [%0], [%1], 16;\n" :: "r"(s), "l"(gmem_src));
}
__device__ __forceinline__ void cp_commit() { asm volatile("cp.async.commit_group;\n"); }
__device__ __forceinline__ void cp_wait0() { asm volatile("cp.async.wait_group 0;\n"); }
__device__ __forceinline__ void cp_wait1() { asm volatile("cp.async.wait_group 1;\n"); }

// ---------------------------------------------------------------------------
// One-time operand rounding kernels
// ---------------------------------------------------------------------------
__global__ void convert_x_kernel(const float* __restrict__ x) {
    const float4* src = reinterpret_cast<const float4*>(x);
    float4* dst = reinterpret_cast<float4*>(g_X);
    const int stride = gridDim.x * blockDim.x;
    for (int i = blockIdx.x * blockDim.x + threadIdx.x; i < 786432; i += stride) {
        float4 v = src[i];
        v.x = tf32f(v.x); v.y = tf32f(v.y); v.z = tf32f(v.z); v.w = tf32f(v.w);
        dst[i] = v;
    }
}

__global__ void convert_w_kernel(const float* __restrict__ qw, const float* __restrict__ kvw,
                                 const float* __restrict__ pw, const float* __restrict__ qb,
                                 const float* __restrict__ kvb) {
    const float scale = 0.17677669529663687f;  // 32^-0.5 folded into Q path
    const int stride = gridDim.x * blockDim.x;
    const int t = blockIdx.x * blockDim.x + threadIdx.x;
    for (int i = t; i < 147456; i += stride) g_Wqkv[i] = tf32f(qw[i] * scale);
    for (int i = t; i < 294912; i += stride) g_Wqkv[147456 + i] = tf32f(kvw[i]);
    for (int i = t; i < 147456; i += stride) g_Wp[i] = tf32f(pw[i]);
    for (int i = t; i < 384; i += stride) g_Bqkv[i] = qb[i] * scale;
    for (int i = t; i < 768; i += stride) g_Bqkv[384 + i] = kvb[i];
}

// ---------------------------------------------------------------------------
// Batched GEMM, cp.async 2-stage pipeline, operands pre-rounded to tf32.
// C[b][m][n] = sum_k W[m][k] * X[b][k][n] + bias[m].  K=384, N=1024.
// Tiles 128x128, k-chunk 32, 8 warps. ROUND: tf32-round the stored output.
// ---------------------------------------------------------------------------
constexpr int GEMM_SMEM_BYTES = 2 * (128 * 36 + 32 * 136) * 4;  // 71,680

template <bool ROUND>
__global__ __launch_bounds__(256, 2)
void gemm_async_kernel(const float* __restrict__ W, const float* __restrict__ X,
                       const float* __restrict__ bias, float* __restrict__ C,
                       long xStride, long cStride) {
    extern __shared__ float sm[];
    float* As = sm;                 // [2][128*36]
    float* Bs = sm + 2 * 128 * 36;  // [2][32*136]

    const int b  = blockIdx.z;
    const int m0 = blockIdx.y * 128;
    const int n0 = blockIdx.x * 128;
    const float* Xb = X + (long)b * xStride;
    float*       Cb = C + (long)b * cStride;

    const int tid  = threadIdx.x;
    const int warp = tid >> 5, lane = tid & 31;
    const int gr = lane >> 2, tc = lane & 3;

    auto issue_tile = [&](int kt) {
        float* A  = As + (kt & 1) * (128 * 36);
        float* Bt = Bs + (kt & 1) * (32 * 136);
        const int k0 = kt * 32;
#pragma unroll
        for (int i = 0; i < 4; i++) {
            int idx = tid + i * 256;          // 1024 16B chunks for A (128x32)
            int r = idx >> 3, cc = (idx & 7) << 2;
            cp_async16(A + r * 36 + cc, W + (long)(m0 + r) * 384 + k0 + cc);
        }
#pragma unroll
        for (int i = 0; i < 4; i++) {
            int idx = tid + i * 256;          // 1024 16B chunks for B (32x128)
            int r = idx >> 5, cc = (idx & 31) << 2;
            cp_async16(Bt + r * 136 + cc, Xb + (long)(k0 + r) * 1024 + n0 + cc);
        }
        cp_commit();
    };

    float acc[16][4];
#pragma unroll
    for (int i = 0; i < 16; i++) { acc[i][0] = 0.f; acc[i][1] = 0.f; acc[i][2] = 0.f; acc[i][3] = 0.f; }

    issue_tile(0);
    issue_tile(1);

    for (int kt = 0; kt < 12; kt++) {
        if (kt < 11) cp_wait1(); else cp_wait0();
        __syncthreads();

        float* A  = As + (kt & 1) * (128 * 36);
        float* Bt = Bs + (kt & 1) * (32 * 136);
#pragma unroll
        for (int ks = 0; ks < 4; ks++) {
            const int kk = ks * 8;
            const int ar = warp * 16 + gr;
            unsigned a0 = __float_as_uint(A[ar * 36 + kk + tc]);
            unsigned a1 = __float_as_uint(A[(ar + 8) * 36 + kk + tc]);
            unsigned a2 = __float_as_uint(A[ar * 36 + kk + tc + 4]);
            unsigned a3 = __float_as_uint(A[(ar + 8) * 36 + kk + tc + 4]);
#pragma unroll
            for (int nt = 0; nt < 16; nt++) {
                unsigned b0 = __float_as_uint(Bt[(kk + tc) * 136 + nt * 8 + gr]);
                unsigned b1 = __float_as_uint(Bt[(kk + tc + 4) * 136 + nt * 8 + gr]);
                mma_tf32(acc[nt], a0, a1, a2, a3, b0, b1);
            }
        }
        __syncthreads();
        if (kt + 2 < 12) issue_tile(kt + 2);
    }

    const int r0 = m0 + warp * 16 + gr;
    const float bz0 = bias[r0], bz1 = bias[r0 + 8];
#pragma unroll
    for (int nt = 0; nt < 16; nt++) {
        const int cc = n0 + nt * 8 + tc * 2;
        float o00 = acc[nt][0] + bz0, o01 = acc[nt][1] + bz0;
        float o10 = acc[nt][2] + bz1, o11 = acc[nt][3] + bz1;
        if (ROUND) { o00 = tf32f(o00); o01 = tf32f(o01); o10 = tf32f(o10); o11 = tf32f(o11); }
        *reinterpret_cast<float2*>(Cb + (long)r0 * 1024 + cc)       = make_float2(o00, o01);
        *reinterpret_cast<float2*>(Cb + (long)(r0 + 8) * 1024 + cc) = make_float2(o10, o11);
    }
}

// ---------------------------------------------------------------------------
// Flash attention: cp.async double-buffered K/V, P kept in registers and
// converted C-frag -> A-frag via quad shuffles (no Ps smem). Analytic bias.
// Grid: (qblock 0..7, head 0..11, batch 0..7). 256 threads, 2 CTAs/SM.
// ---------------------------------------------------------------------------
constexpr int A_QS  = 0;                    // 32*136 = 4352
constexpr int A_KS  = 4352;                 // 2 stages * 4352
constexpr int A_VS  = A_KS + 2 * 4352;      // 2 stages * 4224
constexpr int A_RPB = A_VS + 2 * 4224;      // 3969
constexpr int ATTN_SMEM_BYTES = (A_RPB + 3969) * 4;  // 101,892 B

__global__ __launch_bounds__(256, 2)
void attn_async_kernel(const float* __restrict__ rpb_table, float* __restrict__ Oout) {
    extern __shared__ float sm[];
    float* Qs    = sm + A_QS;
    float* Ksb   = sm + A_KS;
    float* Vsb   = sm + A_VS;
    float* rpb_s = sm + A_RPB;

    const int qb = blockIdx.x, h = blockIdx.y, b = blockIdx.z;
    const int tid  = threadIdx.x;
    const int warp = tid >> 5, lane = tid & 31;
    const int gr = lane >> 2, tc = lane & 3;

    const float* Qg = g_Y + ((long)b * 1152 + h * 32) * 1024 + qb * 128;
    const float* Kg = g_Y + ((long)b * 1152 + 384 + h * 32) * 1024;
    const float* Vg = g_Y + ((long)b * 1152 + 768 + h * 32) * 1024;

    // Group 0: full Q tile [32][128] + full K/V block 0 (4 x 16B chunks each)
#pragma unroll
    for (int i = 0; i < 4; i++) {
        int idx = tid + i * 256;
        int d = idx >> 5, c4 = (idx & 31) << 2;
        const long off = (long)d * 1024 + c4;
        cp_async16(Qs + d * 136 + c4, Qg + off);
        cp_async16(Ksb + d * 136 + c4, Kg + off);
        cp_async16(Vsb + d * 132 + c4, Vg + off);
    }
    cp_commit();

    // Per-head bias column into shared (stride-12 gather)
    for (int i = tid; i < 3969; i += 256) rpb_s[i] = rpb_table[i * 12 + h];

    float oacc[4][4];
#pragma unroll
    for (int i = 0; i < 4; i++) { oacc[i][0] = 0.f; oacc[i][1] = 0.f; oacc[i][2] = 0.f; oacc[i][3] = 0.f; }
    float mrun0 = -1e30f, mrun1 = -1e30f, lrun0 = 0.f, lrun1 = 0.f;

    // Hoisted bias row constants: idx = A_row - (m + (m>>5)*31)
    const int n0g = qb * 128 + warp * 16 + gr;
    const int Abias0 = ((n0g >> 5) + 31) * 63 + (n0g & 31) + 31;
    const int n1g = n0g + 8;
    const int Abias1 = ((n1g >> 5) + 31) * 63 + (n1g & 31) + 31;

    const float L2E = 1.4426950408889634f;
    const int s0lane = (lane & 28) | (tc >> 1);   // quad-source lane for A-frag cols tc
    const bool oddc = (tc & 1);

    for (int kb = 0; kb < 8; kb++) {
        if (kb < 7) {
            const int nb = kb + 1;
            float* Kn = Ksb + (nb & 1) * 4352;
            float* Vn = Vsb + (nb & 1) * 4224;
#pragma unroll
            for (int i = 0; i < 4; i++) {
                int idx = tid + i * 256;
                int d = idx >> 5, c4 = (idx & 31) << 2;
                const long off = (long)d * 1024 + nb * 128 + c4;
                cp_async16(Kn + d * 136 + c4, Kg + off);
                cp_async16(Vn + d * 132 + c4, Vg + off);
            }
            cp_commit();
            cp_wait1();
        } else {
            cp_wait0();
        }
        __syncthreads();

        float* Ks = Ksb + (kb & 1) * 4352;
        float* Vs = Vsb + (kb & 1) * 4224;

        // S = Q^T K (warp rows warp*16..+15, 128 key cols)
        float sacc[16][4];
#pragma unroll
        for (int i = 0; i < 16; i++) { sacc[i][0] = 0.f; sacc[i][1] = 0.f; sacc[i][2] = 0.f; sacc[i][3] = 0.f; }

#pragma unroll
        for (int ks = 0; ks < 4; ks++) {
            const int kk = ks * 8;
            const int nb = warp * 16;
            unsigned a0 = __float_as_uint(Qs[(kk + tc) * 136 + nb + gr]);
            unsigned a1 = __float_as_uint(Qs[(kk + tc) * 136 + nb + gr + 8]);
            unsigned a2 = __float_as_uint(Qs[(kk + tc + 4) * 136 + nb + gr]);
            unsigned a3 = __float_as_uint(Qs[(kk + tc + 4) * 136 + nb + gr + 8]);
#pragma unroll
            for (int nt = 0; nt < 16; nt++) {
                unsigned b0 = __float_as_uint(Ks[(kk + tc) * 136 + nt * 8 + gr]);
                unsigned b1 = __float_as_uint(Ks[(kk + tc + 4) * 136 + nt * 8 + gr]);
                mma_tf32(sacc[nt], a0, a1, a2, a3, b0, b1);
            }
        }

        // Analytic relative-position bias
#pragma unroll
        for (int nt = 0; nt < 16; nt++) {
            const int m  = kb * 128 + nt * 8 + tc * 2;
            const int Bm = m + (m >> 5) * 31;
            sacc[nt][0] += rpb_s[Abias0 - Bm];
            sacc[nt][1] += rpb_s[Abias0 - Bm - 1];
            sacc[nt][2] += rpb_s[Abias1 - Bm];
            sacc[nt][3] += rpb_s[Abias1 - Bm - 1];
        }

        // Row max + rescale
        float mx0 = -1e30f, mx1 = -1e30f;
#pragma unroll
        for (int nt = 0; nt < 16; nt++) {
            mx0 = fmaxf(mx0, fmaxf(sacc[nt][0], sacc[nt][1]));
            mx1 = fmaxf(mx1, fmaxf(sacc[nt][2], sacc[nt][3]));
        }
        mx0 = fmaxf(mx0, __shfl_xor_sync(0xffffffffu, mx0, 1));
        mx0 = fmaxf(mx0, __shfl_xor_sync(0xffffffffu, mx0, 2));
        mx1 = fmaxf(mx1, __shfl_xor_sync(0xffffffffu, mx1, 1));
        mx1 = fmaxf(mx1, __shfl_xor_sync(0xffffffffu, mx1, 2));
        const float mnew0 = fmaxf(mrun0, mx0);
        const float mnew1 = fmaxf(mrun1, mx1);
        const float alpha0 = fast_ex2((mrun0 - mnew0) * L2E);
        const float alpha1 = fast_ex2((mrun1 - mnew1) * L2E);
        mrun0 = mnew0; mrun1 = mnew1;
#pragma unroll
        for (int dt = 0; dt < 4; dt++) {
            oacc[dt][0] *= alpha0; oacc[dt][1] *= alpha0;
            oacc[dt][2] *= alpha1; oacc[dt][3] *= alpha1;
        }

        // Fused softmax + PV: each 16x8 S tile -> exp -> A-frag via quad shuffle -> mma
        float sum0 = 0.f, sum1 = 0.f;
#pragma unroll
        for (int nt = 0; nt < 16; nt++) {
            float p0 = fast_ex2((sacc[nt][0] - mnew0) * L2E);
            float p1 = fast_ex2((sacc[nt][1] - mnew0) * L2E);
            float p2 = fast_ex2((sacc[nt][2] - mnew1) * L2E);
            float p3 = fast_ex2((sacc[nt][3] - mnew1) * L2E);
            sum0 += p0 + p1; sum1 += p2 + p3;

            unsigned u0 = tf32_bits(p0), u1 = tf32_bits(p1);
            unsigned u2 = tf32_bits(p2), u3 = tf32_bits(p3);
            unsigned x00 = __shfl_sync(0xffffffffu, u0, s0lane);
            unsigned x01 = __shfl_sync(0xffffffffu, u1, s0lane);
            unsigned x10 = __shfl_sync(0xffffffffu, u2, s0lane);
            unsigned x11 = __shfl_sync(0xffffffffu, u3, s0lane);
            unsigned y00 = __shfl_sync(0xffffffffu, u0, s0lane + 2);
            unsigned y01 = __shfl_sync(0xffffffffu, u1, s0lane + 2);
            unsigned y10 = __shfl_sync(0xffffffffu, u2, s0lane + 2);
            unsigned y11 = __shfl_sync(0xffffffffu, u3, s0lane + 2);
            unsigned a0 = oddc ? x01 : x00;   // P[warp*16+gr][kk+tc]
            unsigned a1 = oddc ? x11 : x10;   // P[warp*16+gr+8][kk+tc]
            unsigned a2 = oddc ? y01 : y00;   // P[warp*16+gr][kk+tc+4]
            unsigned a3 = oddc ? y11 : y10;   // P[warp*16+gr+8][kk+tc+4]

            const int kk = nt * 8;
#pragma unroll
            for (int dt = 0; dt < 4; dt++) {
                unsigned b0 = __float_as_uint(Vs[(dt * 8 + gr) * 132 + kk + tc]);
                unsigned b1 = __float_as_uint(Vs[(dt * 8 + gr) * 132 + kk + tc + 4]);
                mma_tf32(oacc[dt], a0, a1, a2, a3, b0, b1);
            }
        }
        sum0 += __shfl_xor_sync(0xffffffffu, sum0, 1);
        sum0 += __shfl_xor_sync(0xffffffffu, sum0, 2);
        sum1 += __shfl_xor_sync(0xffffffffu, sum1, 1);
        sum1 += __shfl_xor_sync(0xffffffffu, sum1, 2);
        lrun0 = lrun0 * alpha0 + sum0;
        lrun1 = lrun1 * alpha1 + sum1;

        __syncthreads();  // all warps done with Ks/Vs[cur] before it is refilled
    }

    // Finalize: stage transposed into Qs (free now), write [d][n] tf32-rounded
    const float inv0 = 1.f / lrun0;
    const float inv1 = 1.f / lrun1;
    float* Os = Qs;  // [128 n][32 d] stride 33 (4224 <= 4352)
    {
        const int rl = warp * 16 + gr;
#pragma unroll
        for (int dt = 0; dt < 4; dt++) {
            const int cl = dt * 8 + tc * 2;
            Os[rl * 33 + cl]           = oacc[dt][0] * inv0;
            Os[rl * 33 + cl + 1]       = oacc[dt][1] * inv0;
            Os[(rl + 8) * 33 + cl]     = oacc[dt][2] * inv1;
            Os[(rl + 8) * 33 + cl + 1] = oacc[dt][3] * inv1;
        }
    }
    __syncthreads();
    float* Ob = Oout + ((long)b * 384 + h * 32) * 1024 + qb * 128;
    for (int i = tid; i < 4096; i += 256) {
        int d = i >> 7, n = i & 127;
        Ob[(long)d * 1024 + n] = tf32f(Os[n * 33 + d]);
    }
}

// ---------------------------------------------------------------------------
// Launch
// ---------------------------------------------------------------------------
extern "C" void kernel_launch(void* const* d_in, const int* in_sizes, int n_in,
                              void* d_out, int out_size) {
    (void)in_sizes; (void)n_in; (void)out_size;
    const float* x      = (const float*)d_in[0];
    const float* q_w    = (const float*)d_in[1];
    const float* q_b    = (const float*)d_in[2];
    const float* kv_w   = (const float*)d_in[3];
    const float* kv_b   = (const float*)d_in[4];
    const float* proj_w = (const float*)d_in[5];
    const float* proj_b = (const float*)d_in[6];
    const float* rpb    = (const float*)d_in[7];
    // d_in[8] = rel_index: recomputed analytically on device, unused.
    float* out = (float*)d_out;

    float* X = nullptr; cudaGetSymbolAddress((void**)&X, g_X);
    float* Y = nullptr; cudaGetSymbolAddress((void**)&Y, g_Y);
    float* O = nullptr; cudaGetSymbolAddress((void**)&O, g_O);
    float* Wqkv = nullptr; cudaGetSymbolAddress((void**)&Wqkv, g_Wqkv);
    float* Wp   = nullptr; cudaGetSymbolAddress((void**)&Wp, g_Wp);
    float* Bqkv = nullptr; cudaGetSymbolAddress((void**)&Bqkv, g_Bqkv);

    cudaFuncSetAttribute(gemm_async_kernel<true>,
                         cudaFuncAttributeMaxDynamicSharedMemorySize, GEMM_SMEM_BYTES);
    cudaFuncSetAttribute(gemm_async_kernel<false>,
                         cudaFuncAttributeMaxDynamicSharedMemorySize, GEMM_SMEM_BYTES);
    cudaFuncSetAttribute(attn_async_kernel,
                         cudaFuncAttributeMaxDynamicSharedMemorySize, ATTN_SMEM_BYTES);

    dim3 blk(256);
    // Pre-round operands to tf32 so cp.async paths are numerically exact RNA
    convert_x_kernel<<<768, blk>>>(x);
    convert_w_kernel<<<288, blk>>>(q_w, kv_w, proj_w, q_b, kv_b);
    // Fused QKV projection -> g_Y (rounded)
    gemm_async_kernel<true><<<dim3(8, 9, 8), blk, GEMM_SMEM_BYTES>>>(
        Wqkv, X, Bqkv, Y, 384L * 1024, 1152L * 1024);
    // Flash attention -> g_O (rounded)
    attn_async_kernel<<<dim3(8, 12, 8), blk, ATTN_SMEM_BYTES>>>(rpb, O);
    // Output projection -> d_out (not rounded)
    gemm_async_kernel<false><<<dim3(8, 3, 8), blk, GEMM_SMEM_BYTES>>>(
        Wp, O, proj_b, out, 384L * 1024, 384L * 1024);
}

// round 11
// speedup vs baseline: 1.5069x; 1.1797x over previous
#include <cuda_runtime.h>
#include <cstdint>

// ---------------------------------------------------------------------------
// Scratch (static __device__ — no allocation in kernel_launch)
// ---------------------------------------------------------------------------
static __device__ float g_X[8 * 384 * 1024];   // tf32-rounded input activations
static __device__ float g_Y[8 * 1152 * 1024];  // fused QKV output [b][1152][1024] (tf32-rounded)
static __device__ float g_O[8 * 384 * 1024];   // attention output  [b][384][1024] (tf32-rounded)
static __device__ float g_Wqkv[1152 * 384];    // [q_w*scale ; kv_w] tf32-rounded
static __device__ float g_Wp[384 * 384];       // proj_w tf32-rounded
static __device__ float g_Bqkv[1152];          // [q_b*scale ; kv_b]
static __device__ float g_rpbT[12 * 3972];     // rpb_table transposed [head][pad 3972]

// ---------------------------------------------------------------------------
// Helpers
// ---------------------------------------------------------------------------
__device__ __forceinline__ unsigned tf32_bits(float x) {
    unsigned u;
    asm("cvt.rna.tf32.f32 %0, %1;" : "=r"(u) : "f"(x));
    return u;
}
__device__ __forceinline__ float tf32f(float x) { return __uint_as_float(tf32_bits(x)); }

__device__ __forceinline__ float fast_ex2(float x) {
    float y;
    asm("ex2.approx.f32 %0, %1;" : "=f"(y) : "f"(x));
    return y;
}

__device__ __forceinline__ void mma_tf32(float* c,
                                         unsigned a0, unsigned a1, unsigned a2, unsigned a3,
                                         unsigned b0, unsigned b1) {
    asm volatile(
        "mma.sync.aligned.m16n8k8.row.col.f32.tf32.tf32.f32 "
        "{%0,%1,%2,%3}, {%4,%5,%6,%7}, {%8,%9}, {%0,%1,%2,%3};\n"
        : "+f"(c[0]), "+f"(c[1]), "+f"(c[2]), "+f"(c[3])
        : "r"(a0), "r"(a1), "r"(a2), "r"(a3), "r"(b0), "r"(b1));
}

__device__ __forceinline__ void cp_async16(float* smem_dst, const float* gmem_src) {
    unsigned s = (unsigned)__cvta_generic_to_shared(smem_dst);
    asm volatile("cp.async.cg.shared.global [%0], [%1], 16;\n" :: "r"(s), "l"(gmem_src));
}
__device__ __forceinline__ void cp_commit() { asm volatile("cp.async.commit_group;\n"); }
__device__ __forceinline__ void cp_wait0() { asm volatile("cp.async.wait_group 0;\n"); }
__device__ __forceinline__ void cp_wait1() { asm volatile("cp.async.wait_group 1;\n"); }

// ---------------------------------------------------------------------------
// One-time operand rounding / transpose kernels
// ---------------------------------------------------------------------------
__global__ void convert_x_kernel(const float* __restrict__ x) {
    const float4* src = reinterpret_cast<const float4*>(x);
    float4* dst = reinterpret_cast<float4*>(g_X);
    const int stride = gridDim.x * blockDim.x;
    for (int i = blockIdx.x * blockDim.x + threadIdx.x; i < 786432; i += stride) {
        float4 v = src[i];
        v.x = tf32f(v.x); v.y = tf32f(v.y); v.z = tf32f(v.z); v.w = tf32f(v.w);
        dst[i] = v;
    }
}

__global__ void convert_w_kernel(const float* __restrict__ qw, const float* __restrict__ kvw,
                                 const float* __restrict__ pw, const float* __restrict__ qb,
                                 const float* __restrict__ kvb, const float* __restrict__ rpb) {
    const float scale = 0.17677669529663687f;  // 32^-0.5 folded into Q path
    const int stride = gridDim.x * blockDim.x;
    const int t = blockIdx.x * blockDim.x + threadIdx.x;
    for (int i = t; i < 147456; i += stride) g_Wqkv[i] = tf32f(qw[i] * scale);
    for (int i = t; i < 294912; i += stride) g_Wqkv[147456 + i] = tf32f(kvw[i]);
    for (int i = t; i < 147456; i += stride) g_Wp[i] = tf32f(pw[i]);
    for (int i = t; i < 384; i += stride) g_Bqkv[i] = qb[i] * scale;
    for (int i = t; i < 768; i += stride) g_Bqkv[384 + i] = kvb[i];
    for (int i = t; i < 12 * 3969; i += stride) {
        int h = i / 3969, j = i - h * 3969;
        g_rpbT[h * 3972 + j] = rpb[j * 12 + h];
    }
}

// ---------------------------------------------------------------------------
// Batched GEMM, cp.async 2-stage pipeline, operands pre-rounded to tf32.
// C[b][m][n] = sum_k W[m][k] * X[b][k][n] + bias[m].  K=384, N=1024.
// Tiles 128x128, k-chunk 32. 8 warps in a 4(m)x2(n) grid: 32x64 per warp.
// ---------------------------------------------------------------------------
constexpr int GEMM_SMEM_BYTES = 2 * (128 * 36 + 32 * 136) * 4;  // 71,680

template <bool ROUND>
__global__ __launch_bounds__(256, 2)
void gemm_async_kernel(const float* __restrict__ W, const float* __restrict__ X,
                       const float* __restrict__ bias, float* __restrict__ C,
                       long xStride, long cStride) {
    extern __shared__ float sm[];
    float* As = sm;                 // [2][128*36]
    float* Bs = sm + 2 * 128 * 36;  // [2][32*136]

    const int b  = blockIdx.z;
    const int m0 = blockIdx.y * 128;
    const int n0 = blockIdx.x * 128;
    const float* Xb = X + (long)b * xStride;
    float*       Cb = C + (long)b * cStride;

    const int tid  = threadIdx.x;
    const int warp = tid >> 5, lane = tid & 31;
    const int gr = lane >> 2, tc = lane & 3;
    const int mw = warp >> 1, nw = warp & 1;   // warp tile: rows mw*32, cols nw*64

    auto issue_tile = [&](int kt) {
        float* A  = As + (kt & 1) * (128 * 36);
        float* Bt = Bs + (kt & 1) * (32 * 136);
        const int k0 = kt * 32;
#pragma unroll
        for (int i = 0; i < 4; i++) {
            int idx = tid + i * 256;          // 1024 16B chunks for A (128x32)
            int r = idx >> 3, cc = (idx & 7) << 2;
            cp_async16(A + r * 36 + cc, W + (long)(m0 + r) * 384 + k0 + cc);
        }
#pragma unroll
        for (int i = 0; i < 4; i++) {
            int idx = tid + i * 256;          // 1024 16B chunks for B (32x128)
            int r = idx >> 5, cc = (idx & 31) << 2;
            cp_async16(Bt + r * 136 + cc, Xb + (long)(k0 + r) * 1024 + n0 + cc);
        }
        cp_commit();
    };

    float acc[2][8][4];
#pragma unroll
    for (int j = 0; j < 2; j++)
#pragma unroll
        for (int i = 0; i < 8; i++) { acc[j][i][0] = 0.f; acc[j][i][1] = 0.f; acc[j][i][2] = 0.f; acc[j][i][3] = 0.f; }

    issue_tile(0);
    issue_tile(1);

    for (int kt = 0; kt < 12; kt++) {
        if (kt < 11) cp_wait1(); else cp_wait0();
        __syncthreads();

        float* A  = As + (kt & 1) * (128 * 36);
        float* Bt = Bs + (kt & 1) * (32 * 136);
#pragma unroll
        for (int ks = 0; ks < 4; ks++) {
            const int kk = ks * 8;
            unsigned a[2][4];
#pragma unroll
            for (int jt = 0; jt < 2; jt++) {
                const int r = mw * 32 + jt * 16 + gr;
                a[jt][0] = __float_as_uint(A[r * 36 + kk + tc]);
                a[jt][1] = __float_as_uint(A[(r + 8) * 36 + kk + tc]);
                a[jt][2] = __float_as_uint(A[r * 36 + kk + tc + 4]);
                a[jt][3] = __float_as_uint(A[(r + 8) * 36 + kk + tc + 4]);
            }
#pragma unroll
            for (int nt = 0; nt < 8; nt++) {
                const int cc = nw * 64 + nt * 8 + gr;
                unsigned b0 = __float_as_uint(Bt[(kk + tc) * 136 + cc]);
                unsigned b1 = __float_as_uint(Bt[(kk + tc + 4) * 136 + cc]);
                mma_tf32(acc[0][nt], a[0][0], a[0][1], a[0][2], a[0][3], b0, b1);
                mma_tf32(acc[1][nt], a[1][0], a[1][1], a[1][2], a[1][3], b0, b1);
            }
        }
        __syncthreads();
        if (kt + 2 < 12) issue_tile(kt + 2);
    }

#pragma unroll
    for (int jt = 0; jt < 2; jt++) {
        const int rb = m0 + mw * 32 + jt * 16 + gr;
        const float bz0 = bias[rb], bz1 = bias[rb + 8];
#pragma unroll
        for (int nt = 0; nt < 8; nt++) {
            const int cc = n0 + nw * 64 + nt * 8 + tc * 2;
            float o00 = acc[jt][nt][0] + bz0, o01 = acc[jt][nt][1] + bz0;
            float o10 = acc[jt][nt][2] + bz1, o11 = acc[jt][nt][3] + bz1;
            if (ROUND) { o00 = tf32f(o00); o01 = tf32f(o01); o10 = tf32f(o10); o11 = tf32f(o11); }
            *reinterpret_cast<float2*>(Cb + (long)rb * 1024 + cc)       = make_float2(o00, o01);
            *reinterpret_cast<float2*>(Cb + (long)(rb + 8) * 1024 + cc) = make_float2(o10, o11);
        }
    }
}

// ---------------------------------------------------------------------------
// Flash attention, shuffle-free P path.
// QK mma feeds permuted key columns (col g <- key perm(g)=(g>>1)|((g&1)<<2)),
// so the S C-frag after exp IS the B-frag of the PV mma  O^T = V * P^T.
// O^T C-frag rows are d-channels -> direct [d][n] global stores, no staging.
// Grid: (qblock 0..7, head 0..11, batch 0..7). 256 threads, 2 CTAs/SM.
// ---------------------------------------------------------------------------
constexpr int A_QS  = 0;                    // 32*136 = 4352
constexpr int A_KS  = 4352;                 // 2 stages * 4352
constexpr int A_VS  = A_KS + 2 * 4352;      // 2 stages * 4224
constexpr int A_RPB = A_VS + 2 * 4224;      // 3972
constexpr int ATTN_SMEM_BYTES = (A_RPB + 3972) * 4;  // 101,904 B

__global__ __launch_bounds__(256, 2)
void attn_async_kernel(float* __restrict__ Oout) {
    extern __shared__ float sm[];
    float* Qs    = sm + A_QS;
    float* Ksb   = sm + A_KS;
    float* Vsb   = sm + A_VS;
    float* rpb_s = sm + A_RPB;

    const int qb = blockIdx.x, h = blockIdx.y, b = blockIdx.z;
    const int tid  = threadIdx.x;
    const int warp = tid >> 5, lane = tid & 31;
    const int gr = lane >> 2, tc = lane & 3;
    const int pcol = (gr >> 1) | ((gr & 1) << 2);   // permuted key column for B-frag

    const float* Qg = g_Y + ((long)b * 1152 + h * 32) * 1024 + qb * 128;
    const float* Kg = g_Y + ((long)b * 1152 + 384 + h * 32) * 1024;
    const float* Vg = g_Y + ((long)b * 1152 + 768 + h * 32) * 1024;

    // Group 0: full Q tile + K/V block 0 + per-head bias row (all cp.async)
#pragma unroll
    for (int i = 0; i < 4; i++) {
        int idx = tid + i * 256;
        int d = idx >> 5, c4 = (idx & 31) << 2;
        const long off = (long)d * 1024 + c4;
        cp_async16(Qs + d * 136 + c4, Qg + off);
        cp_async16(Ksb + d * 136 + c4, Kg + off);
        cp_async16(Vsb + d * 132 + c4, Vg + off);
    }
    {
        const float* rpbh = g_rpbT + h * 3972;
        for (int i = tid * 4; i < 3972; i += 1024)
            cp_async16(rpb_s + i, rpbh + i);
    }
    cp_commit();

    float oaccT[2][2][4];   // [d-tile][q-tile][c0..c3]; O^T[d][q]
#pragma unroll
    for (int mt = 0; mt < 2; mt++)
#pragma unroll
        for (int qt = 0; qt < 2; qt++) { oaccT[mt][qt][0] = 0.f; oaccT[mt][qt][1] = 0.f; oaccT[mt][qt][2] = 0.f; oaccT[mt][qt][3] = 0.f; }
    float mrun0 = -1e30f, mrun1 = -1e30f, lrun0 = 0.f, lrun1 = 0.f;

    // Analytic bias row constants: idx = Abias(q) - Bm(m), Bm = (m>>5)*63 + (m&31)
    const int n0g = qb * 128 + warp * 16 + gr;
    const int Abias0 = ((n0g >> 5) + 31) * 63 + (n0g & 31) + 31;
    const int n1g = n0g + 8;
    const int Abias1 = ((n1g >> 5) + 31) * 63 + (n1g & 31) + 31;

    const float L2E = 1.4426950408889634f;

    for (int kb = 0; kb < 8; kb++) {
        if (kb < 7) {
            const int nb = kb + 1;
            float* Kn = Ksb + (nb & 1) * 4352;
            float* Vn = Vsb + (nb & 1) * 4224;
#pragma unroll
            for (int i = 0; i < 4; i++) {
                int idx = tid + i * 256;
                int d = idx >> 5, c4 = (idx & 31) << 2;
                const long off = (long)d * 1024 + nb * 128 + c4;
                cp_async16(Kn + d * 136 + c4, Kg + off);
                cp_async16(Vn + d * 132 + c4, Vg + off);
            }
            cp_commit();
            cp_wait1();
        } else {
            cp_wait0();
        }
        __syncthreads();

        float* Ks = Ksb + (kb & 1) * 4352;
        float* Vs = Vsb + (kb & 1) * 4224;

        // S = Q^T K with permuted key columns within each 8-wide tile
        float sacc[16][4];
#pragma unroll
        for (int i = 0; i < 16; i++) { sacc[i][0] = 0.f; sacc[i][1] = 0.f; sacc[i][2] = 0.f; sacc[i][3] = 0.f; }

#pragma unroll
        for (int ks = 0; ks < 4; ks++) {
            const int kk = ks * 8;
            const int nb = warp * 16;
            unsigned a0 = __float_as_uint(Qs[(kk + tc) * 136 + nb + gr]);
            unsigned a1 = __float_as_uint(Qs[(kk + tc) * 136 + nb + gr + 8]);
            unsigned a2 = __float_as_uint(Qs[(kk + tc + 4) * 136 + nb + gr]);
            unsigned a3 = __float_as_uint(Qs[(kk + tc + 4) * 136 + nb + gr + 8]);
#pragma unroll
            for (int nt = 0; nt < 16; nt++) {
                unsigned b0 = __float_as_uint(Ks[(kk + tc) * 136 + nt * 8 + pcol]);
                unsigned b1 = __float_as_uint(Ks[(kk + tc + 4) * 136 + nt * 8 + pcol]);
                mma_tf32(sacc[nt], a0, a1, a2, a3, b0, b1);
            }
        }

        // Bias: this thread's cols are j = nt*8 + tc and nt*8 + tc + 4
#pragma unroll
        for (int nt = 0; nt < 16; nt++) {
            const int m  = kb * 128 + nt * 8 + tc;
            const int Bm = (m >> 5) * 63 + (m & 31);
            sacc[nt][0] += rpb_s[Abias0 - Bm];
            sacc[nt][1] += rpb_s[Abias0 - Bm - 4];
            sacc[nt][2] += rpb_s[Abias1 - Bm];
            sacc[nt][3] += rpb_s[Abias1 - Bm - 4];
        }

        // Row max (rows unpermuted: reg0/1 -> row gr, reg2/3 -> row gr+8)
        float mx0 = -1e30f, mx1 = -1e30f;
#pragma unroll
        for (int nt = 0; nt < 16; nt++) {
            mx0 = fmaxf(mx0, fmaxf(sacc[nt][0], sacc[nt][1]));
            mx1 = fmaxf(mx1, fmaxf(sacc[nt][2], sacc[nt][3]));
        }
        mx0 = fmaxf(mx0, __shfl_xor_sync(0xffffffffu, mx0, 1));
        mx0 = fmaxf(mx0, __shfl_xor_sync(0xffffffffu, mx0, 2));
        mx1 = fmaxf(mx1, __shfl_xor_sync(0xffffffffu, mx1, 1));
        mx1 = fmaxf(mx1, __shfl_xor_sync(0xffffffffu, mx1, 2));
        const float mnew0 = fmaxf(mrun0, mx0);
        const float mnew1 = fmaxf(mrun1, mx1);
        const float alpha0 = fast_ex2((mrun0 - mnew0) * L2E);
        const float alpha1 = fast_ex2((mrun1 - mnew1) * L2E);
        mrun0 = mnew0; mrun1 = mnew1;

        // Per-q-column alphas for the O^T accumulator (cols q = 2tc, 2tc+1, +8)
        const float aq0 = __shfl_sync(0xffffffffu, alpha0, 8 * tc);
        const float aq1 = __shfl_sync(0xffffffffu, alpha0, 8 * tc + 4);
        const float aq2 = __shfl_sync(0xffffffffu, alpha1, 8 * tc);
        const float aq3 = __shfl_sync(0xffffffffu, alpha1, 8 * tc + 4);
#pragma unroll
        for (int mt = 0; mt < 2; mt++) {
            oaccT[mt][0][0] *= aq0; oaccT[mt][0][1] *= aq1;
            oaccT[mt][0][2] *= aq0; oaccT[mt][0][3] *= aq1;
            oaccT[mt][1][0] *= aq2; oaccT[mt][1][1] *= aq3;
            oaccT[mt][1][2] *= aq2; oaccT[mt][1][3] *= aq3;
        }

        // exp -> P regs (already B-frag layout) -> O^T += V * P^T
        float sum0 = 0.f, sum1 = 0.f;
#pragma unroll
        for (int nt = 0; nt < 16; nt++) {
            float p0 = fast_ex2((sacc[nt][0] - mnew0) * L2E);  // P[gr][tc]
            float p1 = fast_ex2((sacc[nt][1] - mnew0) * L2E);  // P[gr][tc+4]
            float p2 = fast_ex2((sacc[nt][2] - mnew1) * L2E);  // P[gr+8][tc]
            float p3 = fast_ex2((sacc[nt][3] - mnew1) * L2E);  // P[gr+8][tc+4]
            sum0 += p0 + p1; sum1 += p2 + p3;

            unsigned u0 = tf32_bits(p0), u1 = tf32_bits(p1);
            unsigned u2 = tf32_bits(p2), u3 = tf32_bits(p3);

            const int kk = nt * 8;
#pragma unroll
            for (int mt = 0; mt < 2; mt++) {
                const int r = mt * 16 + gr;
                unsigned a0 = __float_as_uint(Vs[r * 132 + kk + tc]);
                unsigned a1 = __float_as_uint(Vs[(r + 8) * 132 + kk + tc]);
                unsigned a2 = __float_as_uint(Vs[r * 132 + kk + tc + 4]);
                unsigned a3 = __float_as_uint(Vs[(r + 8) * 132 + kk + tc + 4]);
                mma_tf32(oaccT[mt][0], a0, a1, a2, a3, u0, u1);  // q cols 0..7
                mma_tf32(oaccT[mt][1], a0, a1, a2, a3, u2, u3);  // q cols 8..15
            }
        }
        sum0 += __shfl_xor_sync(0xffffffffu, sum0, 1);
        sum0 += __shfl_xor_sync(0xffffffffu, sum0, 2);
        sum1 += __shfl_xor_sync(0xffffffffu, sum1, 1);
        sum1 += __shfl_xor_sync(0xffffffffu, sum1, 2);
        lrun0 = lrun0 * alpha0 + sum0;
        lrun1 = lrun1 * alpha1 + sum1;

        __syncthreads();  // all warps done with Ks/Vs[cur] before refill
    }

    // Finalize: per-q-column 1/l, direct [d][n] stores (O^T rows are d)
    const float inv0 = 1.f / lrun0;
    const float inv1 = 1.f / lrun1;
    const float iq0 = __shfl_sync(0xffffffffu, inv0, 8 * tc);
    const float iq1 = __shfl_sync(0xffffffffu, inv0, 8 * tc + 4);
    const float iq2 = __shfl_sync(0xffffffffu, inv1, 8 * tc);
    const float iq3 = __shfl_sync(0xffffffffu, inv1, 8 * tc + 4);

    float* Ob = Oout + ((long)b * 384 + h * 32) * 1024 + qb * 128 + warp * 16;
#pragma unroll
    for (int mt = 0; mt < 2; mt++) {
#pragma unroll
        for (int qt = 0; qt < 2; qt++) {
            const float sA = qt ? iq2 : iq0;
            const float sB = qt ? iq3 : iq1;
            const int col = qt * 8 + tc * 2;
            const int r   = mt * 16 + gr;
            *reinterpret_cast<float2*>(Ob + (long)r * 1024 + col) =
                make_float2(tf32f(oaccT[mt][qt][0] * sA), tf32f(oaccT[mt][qt][1] * sB));
            *reinterpret_cast<float2*>(Ob + (long)(r + 8) * 1024 + col) =
                make_float2(tf32f(oaccT[mt][qt][2] * sA), tf32f(oaccT[mt][qt][3] * sB));
        }
    }
}

// ---------------------------------------------------------------------------
// Launch
// ---------------------------------------------------------------------------
extern "C" void kernel_launch(void* const* d_in, const int* in_sizes, int n_in,
                              void* d_out, int out_size) {
    (void)in_sizes; (void)n_in; (void)out_size;
    const float* x      = (const float*)d_in[0];
    const float* q_w    = (const float*)d_in[1];
    const float* q_b    = (const float*)d_in[2];
    const float* kv_w   = (const float*)d_in[3];
    const float* kv_b   = (const float*)d_in[4];
    const float* proj_w = (const float*)d_in[5];
    const float* proj_b = (const float*)d_in[6];
    const float* rpb    = (const float*)d_in[7];
    // d_in[8] = rel_index: recomputed analytically on device, unused.
    float* out = (float*)d_out;

    float* X = nullptr; cudaGetSymbolAddress((void**)&X, g_X);
    float* Y = nullptr; cudaGetSymbolAddress((void**)&Y, g_Y);
    float* O = nullptr; cudaGetSymbolAddress((void**)&O, g_O);
    float* Wqkv = nullptr; cudaGetSymbolAddress((void**)&Wqkv, g_Wqkv);
    float* Wp   = nullptr; cudaGetSymbolAddress((void**)&Wp, g_Wp);
    float* Bqkv = nullptr; cudaGetSymbolAddress((void**)&Bqkv, g_Bqkv);

    cudaFuncSetAttribute(gemm_async_kernel<true>,
                         cudaFuncAttributeMaxDynamicSharedMemorySize, GEMM_SMEM_BYTES);
    cudaFuncSetAttribute(gemm_async_kernel<false>,
                         cudaFuncAttributeMaxDynamicSharedMemorySize, GEMM_SMEM_BYTES);
    cudaFuncSetAttribute(attn_async_kernel,
                         cudaFuncAttributeMaxDynamicSharedMemorySize, ATTN_SMEM_BYTES);

    dim3 blk(256);
    // Pre-round operands to tf32 so cp.async paths are numerically exact RNA
    convert_x_kernel<<<768, blk>>>(x);
    convert_w_kernel<<<288, blk>>>(q_w, kv_w, proj_w, q_b, kv_b, rpb);
    // Fused QKV projection -> g_Y (rounded)
    gemm_async_kernel<true><<<dim3(8, 9, 8), blk, GEMM_SMEM_BYTES>>>(
        Wqkv, X, Bqkv, Y, 384L * 1024, 1152L * 1024);
    // Flash attention -> g_O (rounded)
    attn_async_kernel<<<dim3(8, 12, 8), blk, ATTN_SMEM_BYTES>>>(O);
    // Output projection -> d_out (not rounded)
    gemm_async_kernel<false><<<dim3(8, 3, 8), blk, GEMM_SMEM_BYTES>>>(
        Wp, O, proj_b, out, 384L * 1024, 384L * 1024);
}